// round 2
// baseline (speedup 1.0000x reference)
#include <cuda_runtime.h>
#include <cstdint>

// ---------------------------------------------------------------------------
// TemporalAttention: x(2,512,16,32,32) -> qkv -> 8-head f=16 attention -> proj
//
// Layouts:
//   s = b*1024 + hh*32 + ww   (spatial index, 2048 total)
//   x[b][c][f][hh][ww] flat = b*8388608 + c*16384 + f*1024 + (hh*32+ww)
//   g_qkv[(f*2048 + s)][n] n in [0,1536): q|k|v each 512  (f-major rows!)
//   g_att[(f*2048 + s)][j] j in [0,512)
//
// f-major row ordering makes GEMM1's A matrix column-major contiguous in x
// (consecutive s are consecutive addresses), so all loads are vectorized.
// ---------------------------------------------------------------------------

static __device__ float g_qkv[50331648];   // [32768][1536]  192 MB scratch
static __device__ float g_att[16777216];   // [32768][512]    64 MB scratch

__device__ __forceinline__ uint32_t f2tf(float f){
  uint32_t r; asm("cvt.rna.tf32.f32 %0, %1;" : "=r"(r) : "f"(f)); return r;
}

__device__ __forceinline__ void mma_tf32(float* c, const uint32_t* a, const uint32_t* b){
  asm volatile(
    "mma.sync.aligned.m16n8k8.row.col.f32.tf32.tf32.f32 "
    "{%0,%1,%2,%3}, {%4,%5,%6,%7}, {%8,%9}, {%0,%1,%2,%3};"
    : "+f"(c[0]), "+f"(c[1]), "+f"(c[2]), "+f"(c[3])
    : "r"(a[0]), "r"(a[1]), "r"(a[2]), "r"(a[3]), "r"(b[0]), "r"(b[1]));
}

// ---------------------------------------------------------------------------
// GEMM1: qkv[f-major m][n] = x-slice(M=32768,K=512 col-major) @ w_qkv(512,1536)
// Block tile 128x128, K-tile 16, 256 threads (8 warps, 2x4 warp grid).
// As stored [k][m] stride 136 (conflict-free: bank = 8k+m all distinct).
// Bs stored [k][n] stride 136.
// ---------------------------------------------------------------------------
__global__ __launch_bounds__(256) void gemm_qkv_kernel(
    const float* __restrict__ x, const float* __restrict__ w)
{
  __shared__ __align__(16) uint32_t As[2][16][136];
  __shared__ __align__(16) uint32_t Bs[2][16][136];

  const int nt = blockIdx.x;           // 0..11  (N tile, 128 cols)
  const int mt = blockIdx.y;           // 0..255 (M tile)
  const int f  = mt & 15;
  const int sb = mt >> 4;              // 0..15
  const int bb = sb >> 3;              // batch
  const int st = sb & 7;               // s-tile within batch (128 each)

  const float* Ab = x + (size_t)bb * 8388608 + f * 1024 + st * 128; // + k*16384 + m
  const float* Bb = w + nt * 128;                                   // + k*1536 + n

  const int tid  = threadIdx.x;
  const int lane = tid & 31, warp = tid >> 5;
  const int g = lane >> 2, t = lane & 3;
  const int mw = (warp & 1) << 6;      // 0,64
  const int nw = (warp >> 1) << 5;     // 0,32,64,96

  float acc[4][4][4];
  #pragma unroll
  for (int i = 0; i < 4; i++)
    #pragma unroll
    for (int j = 0; j < 4; j++)
      #pragma unroll
      for (int r = 0; r < 4; r++) acc[i][j][r] = 0.f;

  const int ak0 = tid >> 5;            // k row 0..7 (second: +8)
  const int aq0 = (tid & 31) << 2;     // float4 offset along m / n

  float4 ra0, ra1, rb0, rb1;

  #define G1_FETCH(KT)                                                          \
    ra0 = *(const float4*)(Ab + (size_t)((KT)*16 + ak0    ) * 16384 + aq0);     \
    ra1 = *(const float4*)(Ab + (size_t)((KT)*16 + ak0 + 8) * 16384 + aq0);     \
    rb0 = *(const float4*)(Bb + (size_t)((KT)*16 + ak0    ) * 1536  + aq0);     \
    rb1 = *(const float4*)(Bb + (size_t)((KT)*16 + ak0 + 8) * 1536  + aq0);

  #define G1_STAGE(BUF) {                                                       \
    uint4 u;                                                                    \
    u.x=f2tf(ra0.x); u.y=f2tf(ra0.y); u.z=f2tf(ra0.z); u.w=f2tf(ra0.w);         \
    *(uint4*)&As[BUF][ak0    ][aq0] = u;                                        \
    u.x=f2tf(ra1.x); u.y=f2tf(ra1.y); u.z=f2tf(ra1.z); u.w=f2tf(ra1.w);         \
    *(uint4*)&As[BUF][ak0 + 8][aq0] = u;                                        \
    u.x=f2tf(rb0.x); u.y=f2tf(rb0.y); u.z=f2tf(rb0.z); u.w=f2tf(rb0.w);         \
    *(uint4*)&Bs[BUF][ak0    ][aq0] = u;                                        \
    u.x=f2tf(rb1.x); u.y=f2tf(rb1.y); u.z=f2tf(rb1.z); u.w=f2tf(rb1.w);         \
    *(uint4*)&Bs[BUF][ak0 + 8][aq0] = u; }

  G1_FETCH(0);
  G1_STAGE(0);
  __syncthreads();

  #pragma unroll 1
  for (int kt = 0; kt < 32; kt++) {
    const int buf = kt & 1;
    if (kt < 31) { G1_FETCH(kt + 1); }

    #pragma unroll
    for (int ks = 0; ks < 2; ks++) {
      const int kb = ks * 8;
      uint32_t af[4][4], bf[4][2];
      #pragma unroll
      for (int mf = 0; mf < 4; mf++) {
        const int mb = mw + mf * 16 + g;
        af[mf][0] = As[buf][kb + t    ][mb];
        af[mf][1] = As[buf][kb + t    ][mb + 8];
        af[mf][2] = As[buf][kb + t + 4][mb];
        af[mf][3] = As[buf][kb + t + 4][mb + 8];
      }
      #pragma unroll
      for (int nf = 0; nf < 4; nf++) {
        const int nb = nw + nf * 8 + g;
        bf[nf][0] = Bs[buf][kb + t    ][nb];
        bf[nf][1] = Bs[buf][kb + t + 4][nb];
      }
      #pragma unroll
      for (int mf = 0; mf < 4; mf++)
        #pragma unroll
        for (int nf = 0; nf < 4; nf++)
          mma_tf32(acc[mf][nf], af[mf], bf[nf]);
    }

    if (kt < 31) { G1_STAGE(buf ^ 1); }
    __syncthreads();
  }
  #undef G1_FETCH
  #undef G1_STAGE

  float* op = g_qkv + (size_t)(f * 2048 + bb * 1024 + st * 128) * 1536 + nt * 128;
  #pragma unroll
  for (int mf = 0; mf < 4; mf++) {
    const int r0 = mw + mf * 16 + g;
    #pragma unroll
    for (int nf = 0; nf < 4; nf++) {
      const int c0 = nw + nf * 8 + t * 2;
      *(float2*)(op + (size_t)r0 * 1536 + c0)       = make_float2(acc[mf][nf][0], acc[mf][nf][1]);
      *(float2*)(op + (size_t)(r0 + 8) * 1536 + c0) = make_float2(acc[mf][nf][2], acc[mf][nf][3]);
    }
  }
}

// ---------------------------------------------------------------------------
// Attention: one block per (s, head). q,k,v are 16x64; stable softmax + bias.
// Pads rows to 65 floats to kill smem bank conflicts on the k[j][*] reads.
// ---------------------------------------------------------------------------
__global__ __launch_bounds__(128) void attn_kernel(const float* __restrict__ pos_bias)
{
  const int s = blockIdx.x;            // 0..2047
  const int h = blockIdx.y;            // 0..7

  __shared__ float qs[16][65];
  __shared__ float ks[16][65];
  __shared__ float vs[16][65];
  __shared__ float sim[16][16];

  const int tid = threadIdx.x;         // 128
  const int d   = tid & 63;
  const int f2  = tid >> 6;            // 0/1

  #pragma unroll
  for (int fi = 0; fi < 8; fi++) {
    const int f = fi * 2 + f2;
    const float* p = g_qkv + (size_t)(f * 2048 + s) * 1536 + h * 64 + d;
    qs[f][d] = p[0] * 0.125f;          // SCALE = 64^-0.5
    ks[f][d] = p[512];
    vs[f][d] = p[1024];
  }
  __syncthreads();

  #pragma unroll
  for (int e = tid; e < 256; e += 128) {
    const int i = e >> 4, j = e & 15;
    float a = 0.f;
    #pragma unroll
    for (int dd = 0; dd < 64; dd++) a += qs[i][dd] * ks[j][dd];
    sim[i][j] = a + pos_bias[h * 256 + i * 16 + j];
  }
  __syncthreads();

  if (tid < 16) {
    float m = sim[tid][0];
    #pragma unroll
    for (int j = 1; j < 16; j++) m = fmaxf(m, sim[tid][j]);
    float e[16], sum = 0.f;
    #pragma unroll
    for (int j = 0; j < 16; j++) { e[j] = expf(sim[tid][j] - m); sum += e[j]; }
    const float inv = 1.f / sum;
    #pragma unroll
    for (int j = 0; j < 16; j++) sim[tid][j] = e[j] * inv;
  }
  __syncthreads();

  #pragma unroll
  for (int fi = 0; fi < 8; fi++) {
    const int f = fi * 2 + f2;
    float o = 0.f;
    #pragma unroll
    for (int j = 0; j < 16; j++) o += sim[f][j] * vs[j][d];
    g_att[(size_t)(f * 2048 + s) * 512 + h * 64 + d] = o;
  }
}

// ---------------------------------------------------------------------------
// GEMM3: out = g_att(32768x512 row-major) @ w_out(512,512), epilogue scatters
// back into the (b,c,f,h,w) layout (contiguous 32B runs along s per store).
// As stored [m][k] stride 20 (bank = 20m+k, all 32 distinct).
// ---------------------------------------------------------------------------
__global__ __launch_bounds__(256) void gemm_out_kernel(
    const float* __restrict__ w, float* __restrict__ out)
{
  __shared__ __align__(16) uint32_t As[2][128][20];
  __shared__ __align__(16) uint32_t Bs[2][16][136];

  const int nt = blockIdx.x;           // 0..3
  const int mt = blockIdx.y;           // 0..255
  const int f  = mt & 15;
  const int sb = mt >> 4;
  const int bb = sb >> 3;
  const int st = sb & 7;

  const float* Ab = g_att + (size_t)(f * 2048 + bb * 1024 + st * 128) * 512;
  const float* Bb = w + nt * 128;

  const int tid  = threadIdx.x;
  const int lane = tid & 31, warp = tid >> 5;
  const int g = lane >> 2, t = lane & 3;
  const int mw = (warp & 1) << 6;
  const int nw = (warp >> 1) << 5;

  float acc[4][4][4];
  #pragma unroll
  for (int i = 0; i < 4; i++)
    #pragma unroll
    for (int j = 0; j < 4; j++)
      #pragma unroll
      for (int r = 0; r < 4; r++) acc[i][j][r] = 0.f;

  const int ar0 = tid >> 2;            // A row 0..63 (second: +64)
  const int ac0 = (tid & 3) << 2;      // k-offset 0,4,8,12
  const int bk0 = tid >> 5;            // B k row 0..7 (second: +8)
  const int bq0 = (tid & 31) << 2;     // B n float4 offset

  float4 ra0, ra1, rb0, rb1;

  #define G3_FETCH(KT)                                                          \
    ra0 = *(const float4*)(Ab + (size_t)(ar0     ) * 512 + (KT)*16 + ac0);      \
    ra1 = *(const float4*)(Ab + (size_t)(ar0 + 64) * 512 + (KT)*16 + ac0);      \
    rb0 = *(const float4*)(Bb + (size_t)((KT)*16 + bk0    ) * 512 + bq0);       \
    rb1 = *(const float4*)(Bb + (size_t)((KT)*16 + bk0 + 8) * 512 + bq0);

  #define G3_STAGE(BUF) {                                                       \
    uint4 u;                                                                    \
    u.x=f2tf(ra0.x); u.y=f2tf(ra0.y); u.z=f2tf(ra0.z); u.w=f2tf(ra0.w);         \
    *(uint4*)&As[BUF][ar0     ][ac0] = u;                                       \
    u.x=f2tf(ra1.x); u.y=f2tf(ra1.y); u.z=f2tf(ra1.z); u.w=f2tf(ra1.w);         \
    *(uint4*)&As[BUF][ar0 + 64][ac0] = u;                                       \
    u.x=f2tf(rb0.x); u.y=f2tf(rb0.y); u.z=f2tf(rb0.z); u.w=f2tf(rb0.w);         \
    *(uint4*)&Bs[BUF][bk0    ][bq0] = u;                                        \
    u.x=f2tf(rb1.x); u.y=f2tf(rb1.y); u.z=f2tf(rb1.z); u.w=f2tf(rb1.w);         \
    *(uint4*)&Bs[BUF][bk0 + 8][bq0] = u; }

  G3_FETCH(0);
  G3_STAGE(0);
  __syncthreads();

  #pragma unroll 1
  for (int kt = 0; kt < 32; kt++) {
    const int buf = kt & 1;
    if (kt < 31) { G3_FETCH(kt + 1); }

    #pragma unroll
    for (int ks = 0; ks < 2; ks++) {
      const int kb = ks * 8;
      uint32_t af[4][4], bf[4][2];
      #pragma unroll
      for (int mf = 0; mf < 4; mf++) {
        const int mb = mw + mf * 16 + g;
        af[mf][0] = As[buf][mb    ][kb + t];
        af[mf][1] = As[buf][mb + 8][kb + t];
        af[mf][2] = As[buf][mb    ][kb + t + 4];
        af[mf][3] = As[buf][mb + 8][kb + t + 4];
      }
      #pragma unroll
      for (int nf = 0; nf < 4; nf++) {
        const int nb = nw + nf * 8 + g;
        bf[nf][0] = Bs[buf][kb + t    ][nb];
        bf[nf][1] = Bs[buf][kb + t + 4][nb];
      }
      #pragma unroll
      for (int mf = 0; mf < 4; mf++)
        #pragma unroll
        for (int nf = 0; nf < 4; nf++)
          mma_tf32(acc[mf][nf], af[mf], bf[nf]);
    }

    if (kt < 31) { G3_STAGE(buf ^ 1); }
    __syncthreads();
  }
  #undef G3_FETCH
  #undef G3_STAGE

  // out[b][c][f][hh][ww]: addr = bb*8388608 + c*16384 + f*1024 + s_local
  float* ob = out + (size_t)bb * 8388608 + f * 1024 + st * 128;
  #pragma unroll
  for (int mf = 0; mf < 4; mf++) {
    const int r0 = mw + mf * 16 + g;
    #pragma unroll
    for (int nf = 0; nf < 4; nf++) {
      const int c0 = nt * 128 + nw + nf * 8 + t * 2;
      ob[(size_t)(c0    ) * 16384 + r0    ] = acc[mf][nf][0];
      ob[(size_t)(c0 + 1) * 16384 + r0    ] = acc[mf][nf][1];
      ob[(size_t)(c0    ) * 16384 + r0 + 8] = acc[mf][nf][2];
      ob[(size_t)(c0 + 1) * 16384 + r0 + 8] = acc[mf][nf][3];
    }
  }
}

// ---------------------------------------------------------------------------
extern "C" void kernel_launch(void* const* d_in, const int* in_sizes, int n_in,
                              void* d_out, int out_size)
{
  (void)in_sizes; (void)n_in; (void)out_size;
  const float* x  = (const float*)d_in[0];
  const float* pb = (const float*)d_in[1];
  const float* wq = (const float*)d_in[2];
  const float* wo = (const float*)d_in[3];
  float* out = (float*)d_out;

  dim3 g1(12, 256);  gemm_qkv_kernel<<<g1, 256>>>(x, wq);
  dim3 ga(2048, 8);  attn_kernel<<<ga, 128>>>(pb);
  dim3 g3(4, 256);   gemm_out_kernel<<<g3, 256>>>(wo, out);
}